// round 15
// baseline (speedup 1.0000x reference)
#include <cuda_runtime.h>
#include <cuda_fp16.h>
#include <cstdint>
#include <math.h>

#define NN 100000
#define DD 512
#define EE 3200000

// ---------------- scratch (__device__ globals) --------------------------------
__device__ __half g_suph[(size_t)NN * DD];   // support in fp16 (gathered a lot)
__device__ __half g_th[(size_t)NN * DD];     // trans in fp16
__device__ __half g_gh[(size_t)NN * DD];     // gate in fp16
__device__ __half g_xh[(size_t)NN * DD];     // x in fp16
__device__ __half g_wh[3 * DD * DD];         // weights in fp16, [z][k][n]
__device__ int    g_deg[NN];
__device__ int    g_cursor[NN];
__device__ int    g_rowptr[NN + 1];
__device__ int2   g_epack[EE];               // packed (col, val bits)

__device__ __forceinline__ uint32_t smem_to_u32(const void* smem_ptr) {
    uint32_t addr;
    asm("{ .reg .u64 tmp; cvta.to.shared.u64 tmp, %1; cvt.u32.u64 %0, tmp; }"
        : "=r"(addr) : "l"(smem_ptr));
    return addr;
}

__device__ __forceinline__ float sigmoidf_(float x) {
    return 1.0f / (1.0f + __expf(-x));
}

// ---------------- CSR build ---------------------------------------------------
__global__ void k_init() {
    int i = blockIdx.x * blockDim.x + threadIdx.x;
    if (i < NN) { g_deg[i] = 0; g_cursor[i] = 0; }
}

__global__ void k_hist(const int* __restrict__ erow) {
    int e = blockIdx.x * blockDim.x + threadIdx.x;
    if (e < EE) atomicAdd(&g_deg[erow[e]], 1);
}

__global__ void k_scan() {
    __shared__ int s[1024];
    const int CH = (NN + 1023) / 1024;
    int t = threadIdx.x;
    int start = t * CH;
    int end = start + CH; if (end > NN) end = NN;
    int sum = 0;
    for (int i = start; i < end; i++) sum += g_deg[i];
    s[t] = sum;
    __syncthreads();
    for (int off = 1; off < 1024; off <<= 1) {
        int v = (t >= off) ? s[t - off] : 0;
        __syncthreads();
        s[t] += v;
        __syncthreads();
    }
    int excl = s[t] - sum;
    for (int i = start; i < end; i++) {
        g_rowptr[i] = excl;
        excl += g_deg[i];
    }
    if (t == 1023) g_rowptr[NN] = s[1023];
}

__global__ void k_scatter(const int* __restrict__ erow,
                          const int* __restrict__ ecol,
                          const float* __restrict__ eval) {
    int e = blockIdx.x * blockDim.x + threadIdx.x;
    if (e < EE) {
        int r = erow[e];
        int pos = g_rowptr[r] + atomicAdd(&g_cursor[r], 1);
        g_epack[pos] = make_int2(ecol[e], __float_as_int(eval[e]));
    }
}

// ---------------- fp32 -> fp16 conversions ------------------------------------
#define NX4 (NN * (DD / 4))
#define NW4 (DD * DD / 4)
#define ROWS_LO 50048                      // 391 m-tiles
#define X4_LO (ROWS_LO * (DD / 4))
#define X4_HI (NX4 - X4_LO)

__device__ __forceinline__ void conv4(const float* src, __half* dst) {
    float4 v = *(const float4*)src;
    __half2 h[2];
    h[0] = __float22half2_rn(make_float2(v.x, v.y));
    h[1] = __float22half2_rn(make_float2(v.z, v.w));
    *(uint2*)dst = *(uint2*)h;
}

// stream A: w1 + x rows [0, ROWS_LO)
__global__ void k_conv_xlo_w1(const float* __restrict__ x,
                              const float* __restrict__ w1) {
    int idx = blockIdx.x * blockDim.x + threadIdx.x;
    if (idx < NW4) {
        conv4(&w1[(size_t)idx * 4], &g_wh[(size_t)idx * 4]);
    } else if (idx < NW4 + X4_LO) {
        int off = idx - NW4;
        conv4(&x[(size_t)off * 4], &g_xh[(size_t)off * 4]);
    }
}

// stream B: x rows [ROWS_LO, NN)
__global__ void k_conv_xhi(const float* __restrict__ x) {
    int idx = blockIdx.x * blockDim.x + threadIdx.x;
    if (idx < X4_HI) {
        size_t off = (size_t)X4_LO + idx;
        conv4(&x[off * 4], &g_xh[off * 4]);
    }
}

__global__ void k_conv_w23(const float* __restrict__ w2,
                           const float* __restrict__ w3) {
    int idx = blockIdx.x * blockDim.x + threadIdx.x;
    if (idx < 2 * NW4) {
        int z = idx / NW4;
        int off = idx - z * NW4;
        const float* w = (z == 0) ? w2 : w3;
        conv4(&w[(size_t)off * 4], &g_wh[(size_t)(z + 1) * DD * DD + (size_t)off * 4]);
    }
}

// ---------------- fp16 mma.sync GEMM, BK=64, 3-stage (proven config) -----------
#define BM 128
#define BN 128
#define BK 64
#define LDA_H 72
#define LDB_H 136
#define A_BYTES (BM * LDA_H * 2)
#define B_BYTES (BK * LDB_H * 2)
#define STAGE_B (A_BYTES + B_BYTES)
#define NSTAGE 3
#define SMEM_GEMM (NSTAGE * STAGE_B)
#define NT (DD / BK)
#define EPI_LD 136                      // epilogue smem stride in halves

__device__ __forceinline__ void cp16(uint32_t dst, const void* src, int sz) {
    asm volatile("cp.async.cg.shared.global [%0], [%1], 16, %2;"
                 :: "r"(dst), "l"(src), "r"(sz));
}

__global__ void __launch_bounds__(256, 2) k_gemm(
    int z, int m_tile_off,
    const float* __restrict__ B2,
    const float* __restrict__ B3) {
    extern __shared__ __align__(128) char smem[];
    const uint32_t sb = smem_to_u32(smem);
    const int tid = threadIdx.x;
    const int wid = tid >> 5;
    const int lane = tid & 31;
    const int warp_m = wid & 3;
    const int warp_n = wid >> 2;
    const int m0 = (blockIdx.y + m_tile_off) * BM;
    const int n0 = blockIdx.x * BN;
    const __half* __restrict__ xh = g_xh;
    const __half* __restrict__ wh = g_wh + (size_t)z * DD * DD;

    auto load_tile = [&](int buf, int kc) {
        const int k0 = kc * BK;
        const uint32_t base = sb + buf * STAGE_B;
        #pragma unroll
        for (int i = 0; i < 4; i++) {
            int idx = tid + i * 256;
            int row = idx >> 3;
            int ch = idx & 7;
            int gr = m0 + row;
            int sz = (gr < NN) ? 16 : 0;
            const __half* src = xh + (size_t)gr * DD + k0 + ch * 8;
            cp16(base + row * (LDA_H * 2) + ch * 16, src, sz);
        }
        #pragma unroll
        for (int i = 0; i < 4; i++) {
            int idx = tid + i * 256;
            int row = idx >> 4;
            int ch = idx & 15;
            const __half* src = wh + (size_t)(k0 + row) * DD + n0 + ch * 8;
            cp16(base + A_BYTES + row * (LDB_H * 2) + ch * 16, src, 16);
        }
        asm volatile("cp.async.commit_group;");
    };

    float c[2][8][4];
    #pragma unroll
    for (int i = 0; i < 2; i++)
        #pragma unroll
        for (int j = 0; j < 8; j++)
            #pragma unroll
            for (int q = 0; q < 4; q++) c[i][j][q] = 0.f;

    load_tile(0, 0);
    load_tile(1, 1);

    for (int kc = 0; kc < NT; kc++) {
        const int buf = kc % NSTAGE;
        if (kc < NT - 1) asm volatile("cp.async.wait_group 1;");
        else             asm volatile("cp.async.wait_group 0;");
        __syncthreads();

        if (kc + 2 < NT) load_tile((kc + 2) % NSTAGE, kc + 2);

        const uint32_t abase = sb + buf * STAGE_B;
        const uint32_t bbase = abase + A_BYTES;

        #pragma unroll
        for (int kk = 0; kk < 4; kk++) {
            uint32_t a[2][4];
            #pragma unroll
            for (int i = 0; i < 2; i++) {
                int row = warp_m * 32 + i * 16 + (lane & 15);
                int col = kk * 16 + (lane >> 4) * 8;
                uint32_t addr = abase + row * (LDA_H * 2) + col * 2;
                asm volatile("ldmatrix.sync.aligned.m8n8.x4.shared.b16 {%0,%1,%2,%3}, [%4];"
                             : "=r"(a[i][0]), "=r"(a[i][1]), "=r"(a[i][2]), "=r"(a[i][3])
                             : "r"(addr));
            }
            uint32_t b[4][4];
            #pragma unroll
            for (int j2 = 0; j2 < 4; j2++) {
                int row = kk * 16 + (lane & 15);
                int col = warp_n * 64 + j2 * 16 + (lane >> 4) * 8;
                uint32_t addr = bbase + row * (LDB_H * 2) + col * 2;
                asm volatile("ldmatrix.sync.aligned.m8n8.x4.trans.shared.b16 {%0,%1,%2,%3}, [%4];"
                             : "=r"(b[j2][0]), "=r"(b[j2][1]), "=r"(b[j2][2]), "=r"(b[j2][3])
                             : "r"(addr));
            }
            #pragma unroll
            for (int i = 0; i < 2; i++) {
                #pragma unroll
                for (int j = 0; j < 8; j++) {
                    const uint32_t* bb = &b[j >> 1][(j & 1) * 2];
                    asm volatile(
                        "mma.sync.aligned.m16n8k16.row.col.f32.f16.f16.f32 "
                        "{%0,%1,%2,%3}, {%4,%5,%6,%7}, {%8,%9}, {%0,%1,%2,%3};"
                        : "+f"(c[i][j][0]), "+f"(c[i][j][1]), "+f"(c[i][j][2]), "+f"(c[i][j][3])
                        : "r"(a[i][0]), "r"(a[i][1]), "r"(a[i][2]), "r"(a[i][3]),
                          "r"(bb[0]), "r"(bb[1]));
                }
            }
        }
    }

    // ---- epilogue: activation in regs -> smem stage -> coalesced 16B stores
    __syncthreads();                     // all warps done reading stage buffers
    __half* sx = (__half*)smem;          // 128 x EPI_LD halves (34.8 KB)

    #pragma unroll
    for (int i = 0; i < 2; i++) {
        int rl = warp_m * 32 + i * 16 + (lane >> 2);
        #pragma unroll
        for (int j = 0; j < 8; j++) {
            int cl = warp_n * 64 + j * 8 + (lane & 3) * 2;
            float v0 = c[i][j][0], v1 = c[i][j][1];
            float v2 = c[i][j][2], v3 = c[i][j][3];
            __half2 h0, h1;
            if (z == 0) {
                h0 = __float22half2_rn(make_float2(v0, v1));
                h1 = __float22half2_rn(make_float2(v2, v3));
            } else if (z == 1) {
                float bx = __ldg(&B2[n0 + cl]), by = __ldg(&B2[n0 + cl + 1]);
                h0 = __float22half2_rn(make_float2(v0 + bx, v1 + by));
                h1 = __float22half2_rn(make_float2(v2 + bx, v3 + by));
            } else {
                float bx = __ldg(&B3[n0 + cl]), by = __ldg(&B3[n0 + cl + 1]);
                h0 = __float22half2_rn(make_float2(sigmoidf_(v0 + bx), sigmoidf_(v1 + by)));
                h1 = __float22half2_rn(make_float2(sigmoidf_(v2 + bx), sigmoidf_(v3 + by)));
            }
            *(__half2*)&sx[rl * EPI_LD + cl]       = h0;
            *(__half2*)&sx[(rl + 8) * EPI_LD + cl] = h1;
        }
    }
    __syncthreads();

    __half* dst = (z == 0) ? g_suph : ((z == 1) ? g_th : g_gh);
    #pragma unroll
    for (int t = 0; t < 8; t++) {
        int idx = tid + t * 256;
        int row = idx >> 4;              // 0..127
        int ch = idx & 15;               // 16 chunks of 8 halves
        int gr = m0 + row;
        if (gr < NN) {
            uint4 v = *(uint4*)&sx[row * EPI_LD + ch * 8];
            if (z == 0)
                *(uint4*)&dst[(size_t)gr * DD + n0 + ch * 8] = v;
            else
                __stcs((uint4*)&dst[(size_t)gr * DD + n0 + ch * 8], v);
        }
    }
}

// ---------------- column-blocked SpMM half-pass + fused gated combine ----------
// Streaming (.cs) on once-touched data so the 51MB support half stays L2-hot.
__global__ void __launch_bounds__(256) k_spmm_half(int half,
                                                   const float* __restrict__ b1,
                                                   float* __restrict__ out) {
    int gw = (blockIdx.x * blockDim.x + threadIdx.x) >> 5;
    int lane = threadIdx.x & 31;
    if (gw >= NN) return;
    int s = g_rowptr[gw];
    int e = g_rowptr[gw + 1];

    float acc[8];
    #pragma unroll
    for (int i = 0; i < 8; i++) acc[i] = 0.f;

    const uint4* sup = (const uint4*)g_suph + half * 32;

    int i = s;
    for (; i + 8 <= e; i += 8) {
        int2 ep[8];
        #pragma unroll
        for (int u = 0; u < 8; u++) ep[u] = __ldcs(&g_epack[i + u]);
        uint4 q[8];
        #pragma unroll
        for (int u = 0; u < 8; u++)
            q[u] = __ldg(&sup[(size_t)ep[u].x * 64 + lane]);
        #pragma unroll
        for (int u = 0; u < 8; u++) {
            float v = __int_as_float(ep[u].y);
            const __half2* h = (const __half2*)&q[u];
            #pragma unroll
            for (int j = 0; j < 4; j++) {
                float2 f = __half22float2(h[j]);
                acc[j * 2 + 0] += v * f.x;
                acc[j * 2 + 1] += v * f.y;
            }
        }
    }
    for (; i < e; i++) {
        int2 ep = __ldcs(&g_epack[i]);
        float v = __int_as_float(ep.y);
        uint4 q = __ldg(&sup[(size_t)ep.x * 64 + lane]);
        const __half2* h = (const __half2*)&q;
        #pragma unroll
        for (int j = 0; j < 4; j++) {
            float2 f = __half22float2(h[j]);
            acc[j * 2 + 0] += v * f.x;
            acc[j * 2 + 1] += v * f.y;
        }
    }

    // fused epilogue: relu(acc + b1), gated combine; trans/gate/out are streaming
    size_t ro = (size_t)gw * DD;
    int cb = half * 256 + lane * 8;
    float4 bb0 = *(const float4*)&b1[cb];
    float4 bb1 = *(const float4*)&b1[cb + 4];
    uint4 tu = __ldcs((const uint4*)&g_th[ro + cb]);
    uint4 gu = __ldcs((const uint4*)&g_gh[ro + cb]);
    const __half2* th = (const __half2*)&tu;
    const __half2* gh = (const __half2*)&gu;
    float bbf[8] = {bb0.x, bb0.y, bb0.z, bb0.w, bb1.x, bb1.y, bb1.z, bb1.w};
    float oo[8];
    #pragma unroll
    for (int j = 0; j < 4; j++) {
        float2 t = __half22float2(th[j]);
        float2 g = __half22float2(gh[j]);
        float r0 = fmaxf(acc[j * 2 + 0] + bbf[j * 2 + 0], 0.f);
        float r1 = fmaxf(acc[j * 2 + 1] + bbf[j * 2 + 1], 0.f);
        oo[j * 2 + 0] = t.x + g.x * (r0 - t.x);
        oo[j * 2 + 1] = t.y + g.y * (r1 - t.y);
    }
    __stcs((float4*)&out[ro + cb],     make_float4(oo[0], oo[1], oo[2], oo[3]));
    __stcs((float4*)&out[ro + cb + 4], make_float4(oo[4], oo[5], oo[6], oo[7]));
}

// ---------------- launch -------------------------------------------------------
extern "C" void kernel_launch(void* const* d_in, const int* in_sizes, int n_in,
                              void* d_out, int out_size) {
    const float* x   = (const float*)d_in[0];
    const float* w1  = (const float*)d_in[1];
    const float* w2  = (const float*)d_in[2];
    const float* w3  = (const float*)d_in[3];
    const float* b1  = (const float*)d_in[4];
    const float* b2  = (const float*)d_in[5];
    const float* b3  = (const float*)d_in[6];
    const int*   er  = (const int*)d_in[7];
    const int*   ec  = (const int*)d_in[8];
    const float* ev  = (const float*)d_in[9];
    float* out = (float*)d_out;

    static cudaStream_t sA = nullptr, sB = nullptr;
    static cudaEvent_t evRoot = nullptr, evCsr = nullptr, evGemm = nullptr,
                       evW23 = nullptr, evXhi = nullptr;
    if (!sA) {
        cudaStreamCreateWithFlags(&sA, cudaStreamNonBlocking);
        cudaStreamCreateWithFlags(&sB, cudaStreamNonBlocking);
        cudaEventCreateWithFlags(&evRoot, cudaEventDisableTiming);
        cudaEventCreateWithFlags(&evCsr, cudaEventDisableTiming);
        cudaEventCreateWithFlags(&evGemm, cudaEventDisableTiming);
        cudaEventCreateWithFlags(&evW23, cudaEventDisableTiming);
        cudaEventCreateWithFlags(&evXhi, cudaEventDisableTiming);
        cudaFuncSetAttribute(k_gemm, cudaFuncAttributeMaxDynamicSharedMemorySize, SMEM_GEMM);
    }

    // fork from the capture-origin stream
    cudaEventRecord(evRoot, 0);
    cudaStreamWaitEvent(sA, evRoot, 0);
    cudaStreamWaitEvent(sB, evRoot, 0);

    const int TILES_LO = ROWS_LO / BM;                          // 391
    const int TILES_HI = (NN + BM - 1) / BM - TILES_LO;         // 391
    dim3 glo(DD / BN, TILES_LO);
    dim3 ghi(DD / BN, TILES_HI);
    dim3 gfull(DD / BN, (NN + BM - 1) / BM);

    // --- stream B: x-high conversion, w2/w3 conversion, CSR build
    k_conv_xhi<<<(X4_HI + 255) / 256, 256, 0, sB>>>(x);
    cudaEventRecord(evXhi, sB);
    k_conv_w23<<<(2 * NW4 + 255) / 256, 256, 0, sB>>>(w2, w3);
    cudaEventRecord(evW23, sB);
    k_init<<<(NN + 255) / 256, 256, 0, sB>>>();
    k_hist<<<(EE + 255) / 256, 256, 0, sB>>>(er);
    k_scan<<<1, 1024, 0, sB>>>();
    k_scatter<<<(EE + 255) / 256, 256, 0, sB>>>(er, ec, ev);
    cudaEventRecord(evCsr, sB);

    // --- stream A: w1 + x-low conversion, then GEMMs (gemm0 split in halves)
    k_conv_xlo_w1<<<(NW4 + X4_LO + 255) / 256, 256, 0, sA>>>(x, w1);
    k_gemm<<<glo, 256, SMEM_GEMM, sA>>>(0, 0, b2, b3);            // support low
    cudaStreamWaitEvent(sA, evXhi, 0);
    k_gemm<<<ghi, 256, SMEM_GEMM, sA>>>(0, TILES_LO, b2, b3);     // support high
    cudaStreamWaitEvent(sA, evW23, 0);
    k_gemm<<<gfull, 256, SMEM_GEMM, sA>>>(1, 0, b2, b3);          // trans
    k_gemm<<<gfull, 256, SMEM_GEMM, sA>>>(2, 0, b2, b3);          // gate
    cudaEventRecord(evGemm, sA);

    // --- origin stream: solo column-blocked SpMM passes with fused combine
    cudaStreamWaitEvent(0, evCsr, 0);
    cudaStreamWaitEvent(0, evGemm, 0);
    int warps_per_block = 8;
    int blocks = (NN + warps_per_block - 1) / warps_per_block;
    k_spmm_half<<<blocks, warps_per_block * 32>>>(0, b1, out);
    k_spmm_half<<<blocks, warps_per_block * 32>>>(1, b1, out);
}

// round 16
// speedup vs baseline: 1.2789x; 1.2789x over previous
#include <cuda_runtime.h>
#include <cuda_fp16.h>
#include <cstdint>
#include <math.h>

#define NN 100000
#define DD 512
#define EE 3200000

// ---------------- scratch (__device__ globals) --------------------------------
__device__ __half g_suph[(size_t)NN * DD];   // support in fp16 (gathered a lot)
__device__ __half g_th[(size_t)NN * DD];     // trans in fp16
__device__ __half g_gh[(size_t)NN * DD];     // gate in fp16
__device__ __half g_xh[(size_t)NN * DD];     // x in fp16
__device__ __half g_wh[3 * DD * DD];         // weights in fp16, [z][k][n]
__device__ int    g_deg[NN];
__device__ int    g_cursor[NN];
__device__ int    g_rowptr[NN + 1];
__device__ int2   g_epack[EE];               // packed (col, val bits)

__device__ __forceinline__ uint32_t smem_to_u32(const void* smem_ptr) {
    uint32_t addr;
    asm("{ .reg .u64 tmp; cvta.to.shared.u64 tmp, %1; cvt.u32.u64 %0, tmp; }"
        : "=r"(addr) : "l"(smem_ptr));
    return addr;
}

__device__ __forceinline__ float sigmoidf_(float x) {
    return 1.0f / (1.0f + __expf(-x));
}

// ---------------- CSR build ---------------------------------------------------
__global__ void k_init() {
    int i = blockIdx.x * blockDim.x + threadIdx.x;
    if (i < NN) { g_deg[i] = 0; g_cursor[i] = 0; }
}

__global__ void k_hist(const int* __restrict__ erow) {
    int e = blockIdx.x * blockDim.x + threadIdx.x;
    if (e < EE) atomicAdd(&g_deg[erow[e]], 1);
}

__global__ void k_scan() {
    __shared__ int s[1024];
    const int CH = (NN + 1023) / 1024;
    int t = threadIdx.x;
    int start = t * CH;
    int end = start + CH; if (end > NN) end = NN;
    int sum = 0;
    for (int i = start; i < end; i++) sum += g_deg[i];
    s[t] = sum;
    __syncthreads();
    for (int off = 1; off < 1024; off <<= 1) {
        int v = (t >= off) ? s[t - off] : 0;
        __syncthreads();
        s[t] += v;
        __syncthreads();
    }
    int excl = s[t] - sum;
    for (int i = start; i < end; i++) {
        g_rowptr[i] = excl;
        excl += g_deg[i];
    }
    if (t == 1023) g_rowptr[NN] = s[1023];
}

__global__ void k_scatter(const int* __restrict__ erow,
                          const int* __restrict__ ecol,
                          const float* __restrict__ eval) {
    int e = blockIdx.x * blockDim.x + threadIdx.x;
    if (e < EE) {
        int r = erow[e];
        int pos = g_rowptr[r] + atomicAdd(&g_cursor[r], 1);
        g_epack[pos] = make_int2(ecol[e], __float_as_int(eval[e]));
    }
}

// ---------------- fp32 -> fp16 conversions ------------------------------------
#define NX4 (NN * (DD / 4))
#define NW4 (DD * DD / 4)
__global__ void k_conv_xw1(const float* __restrict__ x,
                           const float* __restrict__ w1) {
    int idx = blockIdx.x * blockDim.x + threadIdx.x;
    if (idx < NX4) {
        float4 v = *(const float4*)&x[(size_t)idx * 4];
        __half2 h[2];
        h[0] = __float22half2_rn(make_float2(v.x, v.y));
        h[1] = __float22half2_rn(make_float2(v.z, v.w));
        *(uint2*)&g_xh[(size_t)idx * 4] = *(uint2*)h;
    } else if (idx < NX4 + NW4) {
        int off = idx - NX4;
        float4 v = *(const float4*)&w1[(size_t)off * 4];
        __half2 h[2];
        h[0] = __float22half2_rn(make_float2(v.x, v.y));
        h[1] = __float22half2_rn(make_float2(v.z, v.w));
        *(uint2*)&g_wh[(size_t)off * 4] = *(uint2*)h;
    }
}

__global__ void k_conv_w23(const float* __restrict__ w2,
                           const float* __restrict__ w3) {
    int idx = blockIdx.x * blockDim.x + threadIdx.x;
    if (idx < 2 * NW4) {
        int z = idx / NW4;
        int off = idx - z * NW4;
        const float* w = (z == 0) ? w2 : w3;
        float4 v = *(const float4*)&w[(size_t)off * 4];
        __half2 h[2];
        h[0] = __float22half2_rn(make_float2(v.x, v.y));
        h[1] = __float22half2_rn(make_float2(v.z, v.w));
        *(uint2*)&g_wh[(size_t)(z + 1) * DD * DD + (size_t)off * 4] = *(uint2*)h;
    }
}

// ---------------- fp16 mma.sync GEMM, BK=64, 3-stage (proven config) -----------
#define BM 128
#define BN 128
#define BK 64
#define LDA_H 72
#define LDB_H 136
#define A_BYTES (BM * LDA_H * 2)
#define B_BYTES (BK * LDB_H * 2)
#define STAGE_B (A_BYTES + B_BYTES)
#define NSTAGE 3
#define SMEM_GEMM (NSTAGE * STAGE_B)
#define NT (DD / BK)
#define EPI_LD 136                      // epilogue smem stride in halves

__device__ __forceinline__ void cp16(uint32_t dst, const void* src, int sz) {
    asm volatile("cp.async.cg.shared.global [%0], [%1], 16, %2;"
                 :: "r"(dst), "l"(src), "r"(sz));
}

__global__ void __launch_bounds__(256, 2) k_gemm(
    int z,
    const float* __restrict__ B2,
    const float* __restrict__ B3) {
    extern __shared__ __align__(128) char smem[];
    const uint32_t sb = smem_to_u32(smem);
    const int tid = threadIdx.x;
    const int wid = tid >> 5;
    const int lane = tid & 31;
    const int warp_m = wid & 3;
    const int warp_n = wid >> 2;
    const int m0 = blockIdx.y * BM;
    const int n0 = blockIdx.x * BN;
    const __half* __restrict__ xh = g_xh;
    const __half* __restrict__ wh = g_wh + (size_t)z * DD * DD;

    auto load_tile = [&](int buf, int kc) {
        const int k0 = kc * BK;
        const uint32_t base = sb + buf * STAGE_B;
        #pragma unroll
        for (int i = 0; i < 4; i++) {
            int idx = tid + i * 256;
            int row = idx >> 3;
            int ch = idx & 7;
            int gr = m0 + row;
            int sz = (gr < NN) ? 16 : 0;
            const __half* src = xh + (size_t)gr * DD + k0 + ch * 8;
            cp16(base + row * (LDA_H * 2) + ch * 16, src, sz);
        }
        #pragma unroll
        for (int i = 0; i < 4; i++) {
            int idx = tid + i * 256;
            int row = idx >> 4;
            int ch = idx & 15;
            const __half* src = wh + (size_t)(k0 + row) * DD + n0 + ch * 8;
            cp16(base + A_BYTES + row * (LDB_H * 2) + ch * 16, src, 16);
        }
        asm volatile("cp.async.commit_group;");
    };

    float c[2][8][4];
    #pragma unroll
    for (int i = 0; i < 2; i++)
        #pragma unroll
        for (int j = 0; j < 8; j++)
            #pragma unroll
            for (int q = 0; q < 4; q++) c[i][j][q] = 0.f;

    load_tile(0, 0);
    load_tile(1, 1);

    for (int kc = 0; kc < NT; kc++) {
        const int buf = kc % NSTAGE;
        if (kc < NT - 1) asm volatile("cp.async.wait_group 1;");
        else             asm volatile("cp.async.wait_group 0;");
        __syncthreads();

        if (kc + 2 < NT) load_tile((kc + 2) % NSTAGE, kc + 2);

        const uint32_t abase = sb + buf * STAGE_B;
        const uint32_t bbase = abase + A_BYTES;

        #pragma unroll
        for (int kk = 0; kk < 4; kk++) {
            uint32_t a[2][4];
            #pragma unroll
            for (int i = 0; i < 2; i++) {
                int row = warp_m * 32 + i * 16 + (lane & 15);
                int col = kk * 16 + (lane >> 4) * 8;
                uint32_t addr = abase + row * (LDA_H * 2) + col * 2;
                asm volatile("ldmatrix.sync.aligned.m8n8.x4.shared.b16 {%0,%1,%2,%3}, [%4];"
                             : "=r"(a[i][0]), "=r"(a[i][1]), "=r"(a[i][2]), "=r"(a[i][3])
                             : "r"(addr));
            }
            uint32_t b[4][4];
            #pragma unroll
            for (int j2 = 0; j2 < 4; j2++) {
                int row = kk * 16 + (lane & 15);
                int col = warp_n * 64 + j2 * 16 + (lane >> 4) * 8;
                uint32_t addr = bbase + row * (LDB_H * 2) + col * 2;
                asm volatile("ldmatrix.sync.aligned.m8n8.x4.trans.shared.b16 {%0,%1,%2,%3}, [%4];"
                             : "=r"(b[j2][0]), "=r"(b[j2][1]), "=r"(b[j2][2]), "=r"(b[j2][3])
                             : "r"(addr));
            }
            #pragma unroll
            for (int i = 0; i < 2; i++) {
                #pragma unroll
                for (int j = 0; j < 8; j++) {
                    const uint32_t* bb = &b[j >> 1][(j & 1) * 2];
                    asm volatile(
                        "mma.sync.aligned.m16n8k16.row.col.f32.f16.f16.f32 "
                        "{%0,%1,%2,%3}, {%4,%5,%6,%7}, {%8,%9}, {%0,%1,%2,%3};"
                        : "+f"(c[i][j][0]), "+f"(c[i][j][1]), "+f"(c[i][j][2]), "+f"(c[i][j][3])
                        : "r"(a[i][0]), "r"(a[i][1]), "r"(a[i][2]), "r"(a[i][3]),
                          "r"(bb[0]), "r"(bb[1]));
                }
            }
        }
    }

    // ---- epilogue: activation in regs -> smem stage -> coalesced 16B stores
    __syncthreads();                     // all warps done reading stage buffers
    __half* sx = (__half*)smem;          // 128 x EPI_LD halves (34.8 KB)

    #pragma unroll
    for (int i = 0; i < 2; i++) {
        int rl = warp_m * 32 + i * 16 + (lane >> 2);
        #pragma unroll
        for (int j = 0; j < 8; j++) {
            int cl = warp_n * 64 + j * 8 + (lane & 3) * 2;
            float v0 = c[i][j][0], v1 = c[i][j][1];
            float v2 = c[i][j][2], v3 = c[i][j][3];
            __half2 h0, h1;
            if (z == 0) {
                h0 = __float22half2_rn(make_float2(v0, v1));
                h1 = __float22half2_rn(make_float2(v2, v3));
            } else if (z == 1) {
                float bx = __ldg(&B2[n0 + cl]), by = __ldg(&B2[n0 + cl + 1]);
                h0 = __float22half2_rn(make_float2(v0 + bx, v1 + by));
                h1 = __float22half2_rn(make_float2(v2 + bx, v3 + by));
            } else {
                float bx = __ldg(&B3[n0 + cl]), by = __ldg(&B3[n0 + cl + 1]);
                h0 = __float22half2_rn(make_float2(sigmoidf_(v0 + bx), sigmoidf_(v1 + by)));
                h1 = __float22half2_rn(make_float2(sigmoidf_(v2 + bx), sigmoidf_(v3 + by)));
            }
            *(__half2*)&sx[rl * EPI_LD + cl]       = h0;
            *(__half2*)&sx[(rl + 8) * EPI_LD + cl] = h1;
        }
    }
    __syncthreads();

    __half* dst = (z == 0) ? g_suph : ((z == 1) ? g_th : g_gh);
    #pragma unroll
    for (int t = 0; t < 8; t++) {
        int idx = tid + t * 256;
        int row = idx >> 4;              // 0..127
        int ch = idx & 15;               // 16 chunks of 8 halves
        int gr = m0 + row;
        if (gr < NN) {
            uint4 v = *(uint4*)&sx[row * EPI_LD + ch * 8];
            if (z == 0)
                *(uint4*)&dst[(size_t)gr * DD + n0 + ch * 8] = v;
            else
                __stcs((uint4*)&dst[(size_t)gr * DD + n0 + ch * 8], v);
        }
    }
}

// ---------------- column-blocked SpMM half-pass + fused gated combine ----------
// Streaming (.cs) on once-touched data so the 51MB support half stays L2-hot.
__global__ void __launch_bounds__(256) k_spmm_half(int half,
                                                   const float* __restrict__ b1,
                                                   float* __restrict__ out) {
    int gw = (blockIdx.x * blockDim.x + threadIdx.x) >> 5;
    int lane = threadIdx.x & 31;
    if (gw >= NN) return;
    int s = g_rowptr[gw];
    int e = g_rowptr[gw + 1];

    float acc[8];
    #pragma unroll
    for (int i = 0; i < 8; i++) acc[i] = 0.f;

    const uint4* sup = (const uint4*)g_suph + half * 32;

    int i = s;
    for (; i + 8 <= e; i += 8) {
        int2 ep[8];
        #pragma unroll
        for (int u = 0; u < 8; u++) ep[u] = __ldcs(&g_epack[i + u]);
        uint4 q[8];
        #pragma unroll
        for (int u = 0; u < 8; u++)
            q[u] = __ldg(&sup[(size_t)ep[u].x * 64 + lane]);
        #pragma unroll
        for (int u = 0; u < 8; u++) {
            float v = __int_as_float(ep[u].y);
            const __half2* h = (const __half2*)&q[u];
            #pragma unroll
            for (int j = 0; j < 4; j++) {
                float2 f = __half22float2(h[j]);
                acc[j * 2 + 0] += v * f.x;
                acc[j * 2 + 1] += v * f.y;
            }
        }
    }
    for (; i < e; i++) {
        int2 ep = __ldcs(&g_epack[i]);
        float v = __int_as_float(ep.y);
        uint4 q = __ldg(&sup[(size_t)ep.x * 64 + lane]);
        const __half2* h = (const __half2*)&q;
        #pragma unroll
        for (int j = 0; j < 4; j++) {
            float2 f = __half22float2(h[j]);
            acc[j * 2 + 0] += v * f.x;
            acc[j * 2 + 1] += v * f.y;
        }
    }

    // fused epilogue: relu(acc + b1), gated combine; trans/gate/out are streaming
    size_t ro = (size_t)gw * DD;
    int cb = half * 256 + lane * 8;
    float4 bb0 = *(const float4*)&b1[cb];
    float4 bb1 = *(const float4*)&b1[cb + 4];
    uint4 tu = __ldcs((const uint4*)&g_th[ro + cb]);
    uint4 gu = __ldcs((const uint4*)&g_gh[ro + cb]);
    const __half2* th = (const __half2*)&tu;
    const __half2* gh = (const __half2*)&gu;
    float bbf[8] = {bb0.x, bb0.y, bb0.z, bb0.w, bb1.x, bb1.y, bb1.z, bb1.w};
    float oo[8];
    #pragma unroll
    for (int j = 0; j < 4; j++) {
        float2 t = __half22float2(th[j]);
        float2 g = __half22float2(gh[j]);
        float r0 = fmaxf(acc[j * 2 + 0] + bbf[j * 2 + 0], 0.f);
        float r1 = fmaxf(acc[j * 2 + 1] + bbf[j * 2 + 1], 0.f);
        oo[j * 2 + 0] = t.x + g.x * (r0 - t.x);
        oo[j * 2 + 1] = t.y + g.y * (r1 - t.y);
    }
    __stcs((float4*)&out[ro + cb],     make_float4(oo[0], oo[1], oo[2], oo[3]));
    __stcs((float4*)&out[ro + cb + 4], make_float4(oo[4], oo[5], oo[6], oo[7]));
}

// ---------------- launch -------------------------------------------------------
extern "C" void kernel_launch(void* const* d_in, const int* in_sizes, int n_in,
                              void* d_out, int out_size) {
    const float* x   = (const float*)d_in[0];
    const float* w1  = (const float*)d_in[1];
    const float* w2  = (const float*)d_in[2];
    const float* w3  = (const float*)d_in[3];
    const float* b1  = (const float*)d_in[4];
    const float* b2  = (const float*)d_in[5];
    const float* b3  = (const float*)d_in[6];
    const int*   er  = (const int*)d_in[7];
    const int*   ec  = (const int*)d_in[8];
    const float* ev  = (const float*)d_in[9];
    float* out = (float*)d_out;

    static cudaStream_t sA = nullptr, sB = nullptr;
    static cudaEvent_t evRoot = nullptr, evCsr = nullptr, evGemm = nullptr, evW23 = nullptr;
    if (!sA) {
        cudaStreamCreateWithFlags(&sA, cudaStreamNonBlocking);
        cudaStreamCreateWithFlags(&sB, cudaStreamNonBlocking);
        cudaEventCreateWithFlags(&evRoot, cudaEventDisableTiming);
        cudaEventCreateWithFlags(&evCsr, cudaEventDisableTiming);
        cudaEventCreateWithFlags(&evGemm, cudaEventDisableTiming);
        cudaEventCreateWithFlags(&evW23, cudaEventDisableTiming);
        cudaFuncSetAttribute(k_gemm, cudaFuncAttributeMaxDynamicSharedMemorySize, SMEM_GEMM);
    }

    // fork from the capture-origin stream
    cudaEventRecord(evRoot, 0);
    cudaStreamWaitEvent(sA, evRoot, 0);
    cudaStreamWaitEvent(sB, evRoot, 0);

    dim3 ggrid(DD / BN, (NN + BM - 1) / BM);

    // --- stream B: CSR build + w2/w3 conversion (overlaps conv + gemm0 on A)
    k_init<<<(NN + 255) / 256, 256, 0, sB>>>();
    k_hist<<<(EE + 255) / 256, 256, 0, sB>>>(er);
    k_scan<<<1, 1024, 0, sB>>>();
    k_scatter<<<(EE + 255) / 256, 256, 0, sB>>>(er, ec, ev);
    cudaEventRecord(evCsr, sB);
    k_conv_w23<<<(2 * NW4 + 255) / 256, 256, 0, sB>>>(w2, w3);
    cudaEventRecord(evW23, sB);

    // --- stream A: x+w1 conversion, then the three GEMMs (serial tensor work)
    k_conv_xw1<<<(NX4 + NW4 + 255) / 256, 256, 0, sA>>>(x, w1);
    k_gemm<<<ggrid, 256, SMEM_GEMM, sA>>>(0, b2, b3);       // support (fp16)
    cudaStreamWaitEvent(sA, evW23, 0);
    k_gemm<<<ggrid, 256, SMEM_GEMM, sA>>>(1, b2, b3);       // trans  (fp16)
    k_gemm<<<ggrid, 256, SMEM_GEMM, sA>>>(2, b2, b3);       // gate   (fp16)
    cudaEventRecord(evGemm, sA);

    // --- origin stream: solo column-blocked SpMM passes with fused combine
    cudaStreamWaitEvent(0, evCsr, 0);
    cudaStreamWaitEvent(0, evGemm, 0);
    int warps_per_block = 8;
    int blocks = (NN + warps_per_block - 1) / warps_per_block;
    k_spmm_half<<<blocks, warps_per_block * 32>>>(0, b1, out);
    k_spmm_half<<<blocks, warps_per_block * 32>>>(1, b1, out);
}

// round 17
// speedup vs baseline: 1.2916x; 1.0099x over previous
#include <cuda_runtime.h>
#include <cuda_fp16.h>
#include <cstdint>
#include <math.h>

#define NN 100000
#define DD 512
#define EE 3200000

// ---------------- scratch (__device__ globals) --------------------------------
__device__ __half g_suph[(size_t)NN * DD];   // support in fp16 (gathered a lot)
__device__ __half g_th[(size_t)NN * DD];     // trans in fp16
__device__ __half g_gh[(size_t)NN * DD];     // gate in fp16
__device__ __half g_xh[(size_t)NN * DD];     // x in fp16
__device__ __half g_wh[3 * DD * DD];         // weights in fp16, [z][k][n]
__device__ int    g_deg[NN];
__device__ int    g_cursor[NN];
__device__ int    g_rowptr[NN + 1];
__device__ int2   g_epack[EE];               // packed (col, val bits)

__device__ __forceinline__ uint32_t smem_to_u32(const void* smem_ptr) {
    uint32_t addr;
    asm("{ .reg .u64 tmp; cvta.to.shared.u64 tmp, %1; cvt.u32.u64 %0, tmp; }"
        : "=r"(addr) : "l"(smem_ptr));
    return addr;
}

__device__ __forceinline__ float sigmoidf_(float x) {
    return 1.0f / (1.0f + __expf(-x));
}

// ---------------- CSR build ---------------------------------------------------
__global__ void k_init() {
    int i = blockIdx.x * blockDim.x + threadIdx.x;
    if (i < NN) { g_deg[i] = 0; g_cursor[i] = 0; }
}

__global__ void k_hist(const int* __restrict__ erow) {
    int e = blockIdx.x * blockDim.x + threadIdx.x;
    if (e < EE) atomicAdd(&g_deg[erow[e]], 1);
}

__global__ void k_scan() {
    __shared__ int s[1024];
    const int CH = (NN + 1023) / 1024;
    int t = threadIdx.x;
    int start = t * CH;
    int end = start + CH; if (end > NN) end = NN;
    int sum = 0;
    for (int i = start; i < end; i++) sum += g_deg[i];
    s[t] = sum;
    __syncthreads();
    for (int off = 1; off < 1024; off <<= 1) {
        int v = (t >= off) ? s[t - off] : 0;
        __syncthreads();
        s[t] += v;
        __syncthreads();
    }
    int excl = s[t] - sum;
    for (int i = start; i < end; i++) {
        g_rowptr[i] = excl;
        excl += g_deg[i];
    }
    if (t == 1023) g_rowptr[NN] = s[1023];
}

__global__ void k_scatter(const int* __restrict__ erow,
                          const int* __restrict__ ecol,
                          const float* __restrict__ eval) {
    int e = blockIdx.x * blockDim.x + threadIdx.x;
    if (e < EE) {
        int r = erow[e];
        int pos = g_rowptr[r] + atomicAdd(&g_cursor[r], 1);
        g_epack[pos] = make_int2(ecol[e], __float_as_int(eval[e]));
    }
}

// ---------------- fp32 -> fp16 conversions (streaming source reads) ------------
#define NX4 (NN * (DD / 4))
#define NW4 (DD * DD / 4)

__device__ __forceinline__ void conv4_cs(const float* src, __half* dst) {
    float4 v = __ldcs((const float4*)src);
    __half2 h[2];
    h[0] = __float22half2_rn(make_float2(v.x, v.y));
    h[1] = __float22half2_rn(make_float2(v.z, v.w));
    *(uint2*)dst = *(uint2*)h;
}

__global__ void k_conv_xw1(const float* __restrict__ x,
                           const float* __restrict__ w1) {
    int idx = blockIdx.x * blockDim.x + threadIdx.x;
    if (idx < NX4) {
        conv4_cs(&x[(size_t)idx * 4], &g_xh[(size_t)idx * 4]);
    } else if (idx < NX4 + NW4) {
        int off = idx - NX4;
        conv4_cs(&w1[(size_t)off * 4], &g_wh[(size_t)off * 4]);
    }
}

__global__ void k_conv_w23(const float* __restrict__ w2,
                           const float* __restrict__ w3) {
    int idx = blockIdx.x * blockDim.x + threadIdx.x;
    if (idx < 2 * NW4) {
        int z = idx / NW4;
        int off = idx - z * NW4;
        const float* w = (z == 0) ? w2 : w3;
        conv4_cs(&w[(size_t)off * 4], &g_wh[(size_t)(z + 1) * DD * DD + (size_t)off * 4]);
    }
}

// ---------------- fp16 mma.sync GEMM, BK=64, 3-stage (proven config) -----------
#define BM 128
#define BN 128
#define BK 64
#define LDA_H 72
#define LDB_H 136
#define A_BYTES (BM * LDA_H * 2)
#define B_BYTES (BK * LDB_H * 2)
#define STAGE_B (A_BYTES + B_BYTES)
#define NSTAGE 3
#define SMEM_GEMM (NSTAGE * STAGE_B)
#define NT (DD / BK)
#define EPI_LD 136                      // epilogue smem stride in halves

__device__ __forceinline__ void cp16(uint32_t dst, const void* src, int sz) {
    asm volatile("cp.async.cg.shared.global [%0], [%1], 16, %2;"
                 :: "r"(dst), "l"(src), "r"(sz));
}

__global__ void __launch_bounds__(256, 2) k_gemm(
    int z,
    const float* __restrict__ B2,
    const float* __restrict__ B3) {
    extern __shared__ __align__(128) char smem[];
    const uint32_t sb = smem_to_u32(smem);
    const int tid = threadIdx.x;
    const int wid = tid >> 5;
    const int lane = tid & 31;
    const int warp_m = wid & 3;
    const int warp_n = wid >> 2;
    const int m0 = blockIdx.y * BM;
    const int n0 = blockIdx.x * BN;
    const __half* __restrict__ xh = g_xh;
    const __half* __restrict__ wh = g_wh + (size_t)z * DD * DD;

    auto load_tile = [&](int buf, int kc) {
        const int k0 = kc * BK;
        const uint32_t base = sb + buf * STAGE_B;
        #pragma unroll
        for (int i = 0; i < 4; i++) {
            int idx = tid + i * 256;
            int row = idx >> 3;
            int ch = idx & 7;
            int gr = m0 + row;
            int sz = (gr < NN) ? 16 : 0;
            const __half* src = xh + (size_t)gr * DD + k0 + ch * 8;
            cp16(base + row * (LDA_H * 2) + ch * 16, src, sz);
        }
        #pragma unroll
        for (int i = 0; i < 4; i++) {
            int idx = tid + i * 256;
            int row = idx >> 4;
            int ch = idx & 15;
            const __half* src = wh + (size_t)(k0 + row) * DD + n0 + ch * 8;
            cp16(base + A_BYTES + row * (LDB_H * 2) + ch * 16, src, 16);
        }
        asm volatile("cp.async.commit_group;");
    };

    float c[2][8][4];
    #pragma unroll
    for (int i = 0; i < 2; i++)
        #pragma unroll
        for (int j = 0; j < 8; j++)
            #pragma unroll
            for (int q = 0; q < 4; q++) c[i][j][q] = 0.f;

    load_tile(0, 0);
    load_tile(1, 1);

    for (int kc = 0; kc < NT; kc++) {
        const int buf = kc % NSTAGE;
        if (kc < NT - 1) asm volatile("cp.async.wait_group 1;");
        else             asm volatile("cp.async.wait_group 0;");
        __syncthreads();

        if (kc + 2 < NT) load_tile((kc + 2) % NSTAGE, kc + 2);

        const uint32_t abase = sb + buf * STAGE_B;
        const uint32_t bbase = abase + A_BYTES;

        #pragma unroll
        for (int kk = 0; kk < 4; kk++) {
            uint32_t a[2][4];
            #pragma unroll
            for (int i = 0; i < 2; i++) {
                int row = warp_m * 32 + i * 16 + (lane & 15);
                int col = kk * 16 + (lane >> 4) * 8;
                uint32_t addr = abase + row * (LDA_H * 2) + col * 2;
                asm volatile("ldmatrix.sync.aligned.m8n8.x4.shared.b16 {%0,%1,%2,%3}, [%4];"
                             : "=r"(a[i][0]), "=r"(a[i][1]), "=r"(a[i][2]), "=r"(a[i][3])
                             : "r"(addr));
            }
            uint32_t b[4][4];
            #pragma unroll
            for (int j2 = 0; j2 < 4; j2++) {
                int row = kk * 16 + (lane & 15);
                int col = warp_n * 64 + j2 * 16 + (lane >> 4) * 8;
                uint32_t addr = bbase + row * (LDB_H * 2) + col * 2;
                asm volatile("ldmatrix.sync.aligned.m8n8.x4.trans.shared.b16 {%0,%1,%2,%3}, [%4];"
                             : "=r"(b[j2][0]), "=r"(b[j2][1]), "=r"(b[j2][2]), "=r"(b[j2][3])
                             : "r"(addr));
            }
            #pragma unroll
            for (int i = 0; i < 2; i++) {
                #pragma unroll
                for (int j = 0; j < 8; j++) {
                    const uint32_t* bb = &b[j >> 1][(j & 1) * 2];
                    asm volatile(
                        "mma.sync.aligned.m16n8k16.row.col.f32.f16.f16.f32 "
                        "{%0,%1,%2,%3}, {%4,%5,%6,%7}, {%8,%9}, {%0,%1,%2,%3};"
                        : "+f"(c[i][j][0]), "+f"(c[i][j][1]), "+f"(c[i][j][2]), "+f"(c[i][j][3])
                        : "r"(a[i][0]), "r"(a[i][1]), "r"(a[i][2]), "r"(a[i][3]),
                          "r"(bb[0]), "r"(bb[1]));
                }
            }
        }
    }

    // ---- epilogue: activation in regs -> smem stage -> coalesced 16B stores
    __syncthreads();                     // all warps done reading stage buffers
    __half* sx = (__half*)smem;          // 128 x EPI_LD halves (34.8 KB)

    #pragma unroll
    for (int i = 0; i < 2; i++) {
        int rl = warp_m * 32 + i * 16 + (lane >> 2);
        #pragma unroll
        for (int j = 0; j < 8; j++) {
            int cl = warp_n * 64 + j * 8 + (lane & 3) * 2;
            float v0 = c[i][j][0], v1 = c[i][j][1];
            float v2 = c[i][j][2], v3 = c[i][j][3];
            __half2 h0, h1;
            if (z == 0) {
                h0 = __float22half2_rn(make_float2(v0, v1));
                h1 = __float22half2_rn(make_float2(v2, v3));
            } else if (z == 1) {
                float bx = __ldg(&B2[n0 + cl]), by = __ldg(&B2[n0 + cl + 1]);
                h0 = __float22half2_rn(make_float2(v0 + bx, v1 + by));
                h1 = __float22half2_rn(make_float2(v2 + bx, v3 + by));
            } else {
                float bx = __ldg(&B3[n0 + cl]), by = __ldg(&B3[n0 + cl + 1]);
                h0 = __float22half2_rn(make_float2(sigmoidf_(v0 + bx), sigmoidf_(v1 + by)));
                h1 = __float22half2_rn(make_float2(sigmoidf_(v2 + bx), sigmoidf_(v3 + by)));
            }
            *(__half2*)&sx[rl * EPI_LD + cl]       = h0;
            *(__half2*)&sx[(rl + 8) * EPI_LD + cl] = h1;
        }
    }
    __syncthreads();

    __half* dst = (z == 0) ? g_suph : ((z == 1) ? g_th : g_gh);
    #pragma unroll
    for (int t = 0; t < 8; t++) {
        int idx = tid + t * 256;
        int row = idx >> 4;              // 0..127
        int ch = idx & 15;               // 16 chunks of 8 halves
        int gr = m0 + row;
        if (gr < NN) {
            uint4 v = *(uint4*)&sx[row * EPI_LD + ch * 8];
            if (z == 0)
                *(uint4*)&dst[(size_t)gr * DD + n0 + ch * 8] = v;
            else
                __stcs((uint4*)&dst[(size_t)gr * DD + n0 + ch * 8], v);
        }
    }
}

// ---------------- column-blocked SpMM half-pass + fused gated combine ----------
// Gathers use .cg (L2-only, no useless L1 allocation of the 51MB random set);
// once-touched streams use .cs so the support half stays L2-hot.
__global__ void __launch_bounds__(256) k_spmm_half(int half,
                                                   const float* __restrict__ b1,
                                                   float* __restrict__ out) {
    int gw = (blockIdx.x * blockDim.x + threadIdx.x) >> 5;
    int lane = threadIdx.x & 31;
    if (gw >= NN) return;
    int s = g_rowptr[gw];
    int e = g_rowptr[gw + 1];

    float acc[8];
    #pragma unroll
    for (int i = 0; i < 8; i++) acc[i] = 0.f;

    const uint4* sup = (const uint4*)g_suph + half * 32;

    int i = s;
    for (; i + 8 <= e; i += 8) {
        int2 ep[8];
        #pragma unroll
        for (int u = 0; u < 8; u++) ep[u] = __ldcs(&g_epack[i + u]);
        uint4 q[8];
        #pragma unroll
        for (int u = 0; u < 8; u++)
            q[u] = __ldcg(&sup[(size_t)ep[u].x * 64 + lane]);
        #pragma unroll
        for (int u = 0; u < 8; u++) {
            float v = __int_as_float(ep[u].y);
            const __half2* h = (const __half2*)&q[u];
            #pragma unroll
            for (int j = 0; j < 4; j++) {
                float2 f = __half22float2(h[j]);
                acc[j * 2 + 0] += v * f.x;
                acc[j * 2 + 1] += v * f.y;
            }
        }
    }
    for (; i < e; i++) {
        int2 ep = __ldcs(&g_epack[i]);
        float v = __int_as_float(ep.y);
        uint4 q = __ldcg(&sup[(size_t)ep.x * 64 + lane]);
        const __half2* h = (const __half2*)&q;
        #pragma unroll
        for (int j = 0; j < 4; j++) {
            float2 f = __half22float2(h[j]);
            acc[j * 2 + 0] += v * f.x;
            acc[j * 2 + 1] += v * f.y;
        }
    }

    // fused epilogue: relu(acc + b1), gated combine; trans/gate/out are streaming
    size_t ro = (size_t)gw * DD;
    int cb = half * 256 + lane * 8;
    float4 bb0 = *(const float4*)&b1[cb];
    float4 bb1 = *(const float4*)&b1[cb + 4];
    uint4 tu = __ldcs((const uint4*)&g_th[ro + cb]);
    uint4 gu = __ldcs((const uint4*)&g_gh[ro + cb]);
    const __half2* th = (const __half2*)&tu;
    const __half2* gh = (const __half2*)&gu;
    float bbf[8] = {bb0.x, bb0.y, bb0.z, bb0.w, bb1.x, bb1.y, bb1.z, bb1.w};
    float oo[8];
    #pragma unroll
    for (int j = 0; j < 4; j++) {
        float2 t = __half22float2(th[j]);
        float2 g = __half22float2(gh[j]);
        float r0 = fmaxf(acc[j * 2 + 0] + bbf[j * 2 + 0], 0.f);
        float r1 = fmaxf(acc[j * 2 + 1] + bbf[j * 2 + 1], 0.f);
        oo[j * 2 + 0] = t.x + g.x * (r0 - t.x);
        oo[j * 2 + 1] = t.y + g.y * (r1 - t.y);
    }
    __stcs((float4*)&out[ro + cb],     make_float4(oo[0], oo[1], oo[2], oo[3]));
    __stcs((float4*)&out[ro + cb + 4], make_float4(oo[4], oo[5], oo[6], oo[7]));
}

// ---------------- launch -------------------------------------------------------
extern "C" void kernel_launch(void* const* d_in, const int* in_sizes, int n_in,
                              void* d_out, int out_size) {
    const float* x   = (const float*)d_in[0];
    const float* w1  = (const float*)d_in[1];
    const float* w2  = (const float*)d_in[2];
    const float* w3  = (const float*)d_in[3];
    const float* b1  = (const float*)d_in[4];
    const float* b2  = (const float*)d_in[5];
    const float* b3  = (const float*)d_in[6];
    const int*   er  = (const int*)d_in[7];
    const int*   ec  = (const int*)d_in[8];
    const float* ev  = (const float*)d_in[9];
    float* out = (float*)d_out;

    static cudaStream_t sA = nullptr, sB = nullptr;
    static cudaEvent_t evRoot = nullptr, evCsr = nullptr, evGemm = nullptr, evW23 = nullptr;
    if (!sA) {
        cudaStreamCreateWithFlags(&sA, cudaStreamNonBlocking);
        cudaStreamCreateWithFlags(&sB, cudaStreamNonBlocking);
        cudaEventCreateWithFlags(&evRoot, cudaEventDisableTiming);
        cudaEventCreateWithFlags(&evCsr, cudaEventDisableTiming);
        cudaEventCreateWithFlags(&evGemm, cudaEventDisableTiming);
        cudaEventCreateWithFlags(&evW23, cudaEventDisableTiming);
        cudaFuncSetAttribute(k_gemm, cudaFuncAttributeMaxDynamicSharedMemorySize, SMEM_GEMM);
    }

    // fork from the capture-origin stream
    cudaEventRecord(evRoot, 0);
    cudaStreamWaitEvent(sA, evRoot, 0);
    cudaStreamWaitEvent(sB, evRoot, 0);

    dim3 ggrid(DD / BN, (NN + BM - 1) / BM);

    // --- stream B: CSR build + w2/w3 conversion (overlaps conv + gemm0 on A)
    k_init<<<(NN + 255) / 256, 256, 0, sB>>>();
    k_hist<<<(EE + 255) / 256, 256, 0, sB>>>(er);
    k_scan<<<1, 1024, 0, sB>>>();
    k_scatter<<<(EE + 255) / 256, 256, 0, sB>>>(er, ec, ev);
    cudaEventRecord(evCsr, sB);
    k_conv_w23<<<(2 * NW4 + 255) / 256, 256, 0, sB>>>(w2, w3);
    cudaEventRecord(evW23, sB);

    // --- stream A: x+w1 conversion, then the three GEMMs (serial tensor work)
    k_conv_xw1<<<(NX4 + NW4 + 255) / 256, 256, 0, sA>>>(x, w1);
    k_gemm<<<ggrid, 256, SMEM_GEMM, sA>>>(0, b2, b3);       // support (fp16)
    cudaStreamWaitEvent(sA, evW23, 0);
    k_gemm<<<ggrid, 256, SMEM_GEMM, sA>>>(1, b2, b3);       // trans  (fp16)
    k_gemm<<<ggrid, 256, SMEM_GEMM, sA>>>(2, b2, b3);       // gate   (fp16)
    cudaEventRecord(evGemm, sA);

    // --- origin stream: solo column-blocked SpMM passes with fused combine
    cudaStreamWaitEvent(0, evCsr, 0);
    cudaStreamWaitEvent(0, evGemm, 0);
    int warps_per_block = 8;
    int blocks = (NN + warps_per_block - 1) / warps_per_block;
    k_spmm_half<<<blocks, warps_per_block * 32>>>(0, b1, out);
    k_spmm_half<<<blocks, warps_per_block * 32>>>(1, b1, out);
}